// round 17
// baseline (speedup 1.0000x reference)
#include <cuda_runtime.h>
#include <stdint.h>

// Problem shape (fixed)
#define BB    64
#define TT    128
#define CIN   2048
#define COUT  2048
#define NRB   256          // COUT/8 block-rows
#define NCB   256          // CIN/8  block-cols
#define KCAP  48           // max kept blocks per block-row (validated R11)
#define MB    2            // batches per GEMM CTA
#define NTHR  128          // threads per GEMM CTA (4 warps)

#define B_PITCH 400                    // bytes per n-row in smem B (384 data + 16 pad)
#define A_PITCH (MB * 128 + 16)        // 272 bytes per block-col in smem A
#define C_PITCH 10                     // fp32 words per staged C row (even -> STS.64)
#define CBATCH  (TT * C_PITCH + 8)     // 1288 words per batch in C staging
#define COLSTRIDE ((size_t)BB * 128)   // bytes per block-column in g_packed2

// Dynamic smem layout.  A region reused for C staging after the mainloop;
// B region reused for the scan's bit buffer (B is dead after the mainloop).
#define SA_OFF    0
#define SA_BYTES  (KCAP * A_PITCH)            // 13056 (>= MB*CBATCH*4 = 10304)
#define SB_OFF    SA_BYTES
#define SBITS_OFF SB_OFF                      // overlay on dead B region (256B << 3200B)
#define SMEM_G    (SB_OFF + 8 * B_PITCH)      // 16256 -> 14 CTAs/SM (227.6KB)

// Scratch (static device globals — no runtime allocation)
// g_packed2[cb][b][off]: off = h*64 + g*8 + mt*2 + p  for t = h*64 + mt*16 + p*8 + g
__device__ __align__(16) uint8_t g_packed2[(size_t)NCB * BB * TT]; // 2MB
__device__ __align__(16) int8_t  g_Bc[(size_t)NRB * 8 * KCAP * 8]; // interleaved k-order
__device__ uint8_t g_cols[NRB * KCAP];
__device__ int     g_nk[NRB];

// nibble -> float4 of 0/1 (bit j -> component j); static image data, L1-resident
__device__ const float4 g_lut[16] = {
    {0,0,0,0},{1,0,0,0},{0,1,0,0},{1,1,0,0},
    {0,0,1,0},{1,0,1,0},{0,1,1,0},{1,1,1,0},
    {0,0,0,1},{1,0,0,1},{0,1,0,1},{1,1,0,1},
    {0,0,1,1},{1,0,1,1},{0,1,1,1},{1,1,1,1}
};

// ---------------------------------------------------------------------------
// helpers
// ---------------------------------------------------------------------------
__device__ __forceinline__ uint32_t smem_u32(const void* p) {
    uint32_t a;
    asm("{ .reg .u64 t; cvta.to.shared.u64 t, %1; cvt.u32.u64 %0, t; }" : "=r"(a) : "l"(p));
    return a;
}
__device__ __forceinline__ void cp_async16(uint32_t dst, const void* src) {
    asm volatile("cp.async.cg.shared.global [%0], [%1], 16;" :: "r"(dst), "l"(src) : "memory");
}
__device__ __forceinline__ void cp_commit_wait0() {
    asm volatile("cp.async.commit_group;" ::: "memory");
    asm volatile("cp.async.wait_group 0;" ::: "memory");
}
__device__ __forceinline__ void mma_s8(int* c, const uint32_t* a, const uint32_t* b) {
    asm volatile(
        "mma.sync.aligned.m16n8k32.row.col.s32.s8.s8.s32 "
        "{%0,%1,%2,%3}, {%4,%5,%6,%7}, {%8,%9}, {%0,%1,%2,%3};"
        : "+r"(c[0]), "+r"(c[1]), "+r"(c[2]), "+r"(c[3])
        : "r"(a[0]), "r"(a[1]), "r"(a[2]), "r"(a[3]), "r"(b[0]), "r"(b[1]));
}
// expand 4 bits at offset sh of v to 4 bytes of 0/1
__device__ __forceinline__ uint32_t expand_nib(uint32_t v, uint32_t sh) {
    return (((v >> sh) & 0xFu) * 0x00204081u) & 0x01010101u;
}
// exact 2^e for |e| <= 126
__device__ __forceinline__ float exp2i(int e) {
    return __int_as_float((e + 127) << 23);
}

// ---------------------------------------------------------------------------
// Kernel 1 (fused): CTAs [0, NRB) do per-block-row weight compaction (wave 0,
// hidden under the pack waves); CTAs [NRB, NRB+8192) pack spikes.
// ---------------------------------------------------------------------------
__global__ void __launch_bounds__(256) pack_prep_kernel(const float* __restrict__ spikes,
                                                        const float* __restrict__ W,
                                                        const float* __restrict__ M) {
    int bid = blockIdx.x;
    int tid = threadIdx.x;

    if (bid >= NRB) {
        // ---- pack: one byte per (cb, b, t); FFMA-tree byte assembly ----
        // spikes are exactly 0.0f / 1.0f, so byte = lo + 16*hi is exact.
        int pbid = bid - NRB;
        int b  = pbid >> 7;                 // 64 batches
        int cb = (pbid & 127) * 2 + (tid >> 7);
        int t  = tid & 127;
        const float* sp = spikes + ((size_t)b * CIN + cb * 8) * TT + t;
        float v0 = __ldg(sp);
        float v1 = __ldg(sp + (size_t)1 * TT);
        float v2 = __ldg(sp + (size_t)2 * TT);
        float v3 = __ldg(sp + (size_t)3 * TT);
        float v4 = __ldg(sp + (size_t)4 * TT);
        float v5 = __ldg(sp + (size_t)5 * TT);
        float v6 = __ldg(sp + (size_t)6 * TT);
        float v7 = __ldg(sp + (size_t)7 * TT);
        float lo = fmaf(8.0f, v3, fmaf(4.0f, v2, fmaf(2.0f, v1, v0)));
        float hi = fmaf(8.0f, v7, fmaf(4.0f, v6, fmaf(2.0f, v5, v4)));
        int byte = __float2int_rn(fmaf(16.0f, hi, lo));
        // t = h*64 + mt*16 + p*8 + g  ->  off = h*64 + g*8 + mt*2 + p
        int h  = t >> 6;
        int mt = (t >> 4) & 3;
        int p  = (t >> 3) & 1;
        int g  = t & 7;
        int off = h * 64 + g * 8 + mt * 2 + p;
        g_packed2[(size_t)cb * COLSTRIDE + b * 128 + off] = (uint8_t)byte;
        return;
    }

    // ---- prep: ballot-parallel compaction + weight gather (validated R16) ----
    int rb = bid;
    __shared__ uint8_t keptf[NCB];
    __shared__ uint8_t colss[KCAP];
    __shared__ int nks;

    keptf[tid] = (M[(size_t)(rb * 8) * CIN + tid * 8] != 0.0f) ? 1 : 0;
    __syncthreads();
    if (tid < 32) {
        int base = 0;
#pragma unroll
        for (int c8 = 0; c8 < 8; c8++) {
            int c = c8 * 32 + tid;
            bool k = keptf[c] != 0;
            unsigned m = __ballot_sync(0xFFFFFFFFu, k);
            int pos = base + __popc(m & ((1u << tid) - 1u));
            if (k && pos < KCAP) colss[pos] = (uint8_t)c;
            base += __popc(m);
        }
        int n = base < KCAP ? base : KCAP;
        if (tid == 0) { nks = n; g_nk[rb] = n; }
        for (int k = n + (int)tid; k < KCAP; k += 32) colss[k] = 0;
    }
    __syncthreads();
    if (tid < KCAP) g_cols[rb * KCAP + tid] = colss[tid];

    int nk = nks;
    for (int idx = tid; idx < 8 * KCAP * 8; idx += 256) {
        int n = idx / (KCAP * 8), kk = idx % (KCAP * 8);
        int chunk = kk >> 5, w5 = kk & 31;
        int j = (w5 >> 2) & 3;
        int c = (w5 & 3) + 4 * (w5 >> 4);
        int blk = chunk * 4 + j;
        int8_t val = 0;
        if (blk < nk)
            val = (int8_t)__float2int_rn(W[(size_t)(rb * 8 + n) * CIN + colss[blk] * 8 + c]);
        g_Bc[(size_t)rb * (KCAP * 8 * 8) + n * (KCAP * 8) + kk] = val;
    }
}

// ---------------------------------------------------------------------------
// Kernel 2: block-sparse int8 MMA + fused integrate/fire/reset scan.
// CTA = (rb, 2-batch group): M=256, N=8, K = nk*8 compacted.  4 warps:
// warp w = batch w>>1, row-half w&1; thread q owns block-col it*4+q.
// BYTE-IDENTICAL to R16 (best known: 68.4us, tensor 66.8%).
// ---------------------------------------------------------------------------
__global__ void __launch_bounds__(NTHR) sgemm_scan_kernel(const int* __restrict__ scale_exp,
                                                          const int* __restrict__ texp,
                                                          float* __restrict__ out) {
    extern __shared__ __align__(16) uint8_t smem[];
    const uint32_t sbA = smem_u32(smem);

    int tid = threadIdx.x, w = tid >> 5, lane = tid & 31;
    int g = lane >> 2, q = lane & 3;
    int rb = blockIdx.x;
    int b0 = blockIdx.y * MB;

    int nk = __ldg(&g_nk[rb]);
    int nkc = (nk + 3) >> 2;
    const uint8_t* colp = g_cols + rb * KCAP;

    // Stage B (8 rows x KCAP*8 bytes) + A (nk*256B, coalesced 256B per kept col)
    {
        const char* Bg = (const char*)g_Bc + (size_t)rb * (KCAP * 8 * 8);
#pragma unroll
        for (int i = 0; i < 2; i++) {
            int e = tid + i * NTHR;                 // 192 chunks of 16B
            if (e < 8 * (KCAP * 8) / 16) {
                int n = e / (KCAP * 8 / 16), o = e % (KCAP * 8 / 16);
                cp_async16(sbA + SB_OFF + n * B_PITCH + o * 16, Bg + n * (KCAP * 8) + o * 16);
            }
        }
        int nk16 = nk * 16;
        const char* Ag = (const char*)g_packed2 + (size_t)b0 * 128;
        for (int e = tid; e < nk16; e += NTHR) {
            int blk = e >> 4, o2 = e & 15;
            int col = __ldg(colp + blk);
            cp_async16(sbA + SA_OFF + blk * A_PITCH + o2 * 16,
                       Ag + (size_t)col * COLSTRIDE + o2 * 16);
        }
    }
    cp_commit_wait0();
    __syncthreads();

    int acc[4][4];
#pragma unroll
    for (int i = 0; i < 4; i++)
#pragma unroll
        for (int j = 0; j < 4; j++) acc[i][j] = 0;

    // warp w: batch w>>1 (offset *128 in block-col), half h = w&1 (offset *64)
    const uint8_t* sA = smem + SA_OFF + (w >> 1) * 128 + (w & 1) * 64 + g * 8;
    const uint8_t* sBrow = smem + SB_OFF + g * B_PITCH;

    for (int it = 0; it < nkc; it++) {
        uint32_t bf[2];
        bf[0] = *(const uint32_t*)(sBrow + it * 32 + q * 4);
        bf[1] = *(const uint32_t*)(sBrow + it * 32 + q * 4 + 16);
        uint2 v2 = *(const uint2*)(sA + (it * 4 + q) * A_PITCH);  // 4 u16 fragments
#pragma unroll
        for (int mt = 0; mt < 4; mt++) {
            uint32_t src = (mt & 1) ? ((mt & 2) ? (v2.y >> 16) : (v2.x >> 16))
                                    : ((mt & 2) ? v2.y : v2.x);
            uint32_t af[4];
            af[0] = expand_nib(src, 0);   // row r,   ch 0..3
            af[1] = expand_nib(src, 8);   // row r+8, ch 0..3
            af[2] = expand_nib(src, 4);   // row r,   ch 4..7
            af[3] = expand_nib(src, 12);  // row r+8, ch 4..7
            mma_s8(acc[mt], af, bf);
        }
    }
    __syncthreads();   // A and B regions dead; reuse for C staging + bits

    // Stage C into smem fp32 via STS.64 pairs (exact, |acc|<2^18)
    float* sC = (float*)(smem + SA_OFF);
#pragma unroll
    for (int mt = 0; mt < 4; mt++) {
        int lr = (w & 1) * 64 + mt * 16 + g;        // local row within batch w>>1
        float* dst = sC + (size_t)(w >> 1) * CBATCH + lr * C_PITCH + 2 * q;
        float2 lo; lo.x = (float)acc[mt][0]; lo.y = (float)acc[mt][1];
        float2 hi; hi.x = (float)acc[mt][2]; hi.y = (float)acc[mt][3];
        *(float2*)dst = lo;
        *(float2*)(dst + 8 * C_PITCH) = hi;
    }
    __syncthreads();

    // Integrate / fire / reset: 16 scans (2 batches x 8 channels), ONE warp
    uint32_t* sBits = (uint32_t*)(smem + SBITS_OFF);
    if (tid < MB * 8) {
        int ch = tid & 7, bi = tid >> 3;
        float scale = exp2i(__ldg(&scale_exp[rb * 8 + ch]));
        float thr   = exp2i(__ldg(&texp[0]));
        float a = 0.0f;
        uint32_t bits[4] = {0, 0, 0, 0};
        const float* c = sC + (size_t)bi * CBATCH + ch;
#pragma unroll 4
        for (int t = 0; t < TT; t++) {
            a = fmaf(c[t * C_PITCH], scale, a);
            if (a >= thr) { bits[t >> 5] |= 1u << (t & 31); a = 0.0f; }
        }
        sBits[tid * 4 + 0] = bits[0];
        sBits[tid * 4 + 1] = bits[1];
        sBits[tid * 4 + 2] = bits[2];
        sBits[tid * 4 + 3] = bits[3];
    }
    __syncthreads();

    // Output: out[b0+bi][rb*8+ch][t]; nibble -> float4 via L1-resident LUT
#pragma unroll
    for (int i = 0; i < 4; i++) {
        int e = tid + i * NTHR;
        int r = e >> 5, t4 = e & 31;       // r = bi*8+ch
        int bi = r >> 3, ch = r & 7;
        uint32_t word = sBits[r * 4 + (t4 >> 3)];
        uint32_t nib = (word >> ((t4 & 7) * 4)) & 0xFu;
        float4 vv = __ldg(&g_lut[nib]);
        *(float4*)(out + ((size_t)(b0 + bi) * COUT + rb * 8 + ch) * TT + t4 * 4) = vv;
    }
}

// ---------------------------------------------------------------------------
// Inputs: spikes f32 [64,2048,128], weights f32 [2048,2048], mask f32
// [2048,2048], scale_exp i32 [2048], threshold_exp i32 [1].
// Output: f32 [64,2048,128].
// ---------------------------------------------------------------------------
extern "C" void kernel_launch(void* const* d_in, const int* in_sizes, int n_in,
                              void* d_out, int out_size) {
    const float* spikes    = (const float*)d_in[0];
    const float* weights   = (const float*)d_in[1];
    const float* mask      = (const float*)d_in[2];
    const int*   scale_exp = (const int*)d_in[3];
    const int*   texp      = (const int*)d_in[4];
    float*       out       = (float*)d_out;

    pack_prep_kernel<<<NRB + 8192, 256>>>(spikes, weights, mask);
    sgemm_scan_kernel<<<dim3(NRB, BB / MB), NTHR, SMEM_G>>>(scale_exp, texp, out);
}